// round 10
// baseline (speedup 1.0000x reference)
#include <cuda_runtime.h>
#include <cstdint>

// Problem constants (fixed by setup_inputs)
#define N_NODES 8192
#define IN_DIM  256
#define OUT_DIM 64
#define SLOPE   0.2f

// Scratch (allocation-free rule: __device__ globals)
__device__ float g_proj[N_NODES * OUT_DIM];   // 2 MB
__device__ float g_si[N_NODES];
__device__ float g_sj[N_NODES];

// ---------------------------------------------------------------------------
// Kernel 1: proj = X[8192,256] @ W[256,64] + fused s_i/s_j epilogue.
// (R8 version verbatim — measured ~10.4 us, frozen.)
// ---------------------------------------------------------------------------
#define GM_BM 32
#define GM_BK 32
#define AS_LD 36   // 32 + 4 pad

__global__ __launch_bounds__(128) void gemm_proj_kernel(
    const float* __restrict__ X, const float* __restrict__ W,
    const float* __restrict__ a)
{
    __shared__ float As[2][GM_BK * AS_LD];   // [k][m], padded
    __shared__ float Bs[2][GM_BK][OUT_DIM];  // [k][n]
    __shared__ float a_s[2 * OUT_DIM];

    const int tid = threadIdx.x;
    const int block_row = blockIdx.x * GM_BM;
    const int trow = tid >> 4;   // 0..7
    const int tcol = tid & 15;   // 0..15

    a_s[tid] = a[tid];

    const int a_r0 = tid >> 3;
    const int a_c0 = tid & 7;
    const int a_r1 = (tid + 128) >> 3;
    const int b_c4 = tid & 15;
    const int b_r0 = tid >> 4;
    const int b_r1 = (tid + 128) >> 4;
    const int b_r2 = (tid + 256) >> 4;
    const int b_r3 = (tid + 384) >> 4;

    float4 rA0, rA1, rB0, rB1, rB2, rB3;

    auto load_tiles = [&](int k0) {
        rA0 = *(const float4*)(X + (size_t)(block_row + a_r0) * IN_DIM + k0 + a_c0 * 4);
        rA1 = *(const float4*)(X + (size_t)(block_row + a_r1) * IN_DIM + k0 + a_c0 * 4);
        rB0 = *(const float4*)(W + (size_t)(k0 + b_r0) * OUT_DIM + b_c4 * 4);
        rB1 = *(const float4*)(W + (size_t)(k0 + b_r1) * OUT_DIM + b_c4 * 4);
        rB2 = *(const float4*)(W + (size_t)(k0 + b_r2) * OUT_DIM + b_c4 * 4);
        rB3 = *(const float4*)(W + (size_t)(k0 + b_r3) * OUT_DIM + b_c4 * 4);
    };
    auto store_tiles = [&](int buf) {
        As[buf][(a_c0 * 4 + 0) * AS_LD + a_r0] = rA0.x;
        As[buf][(a_c0 * 4 + 1) * AS_LD + a_r0] = rA0.y;
        As[buf][(a_c0 * 4 + 2) * AS_LD + a_r0] = rA0.z;
        As[buf][(a_c0 * 4 + 3) * AS_LD + a_r0] = rA0.w;
        As[buf][(a_c0 * 4 + 0) * AS_LD + a_r1] = rA1.x;
        As[buf][(a_c0 * 4 + 1) * AS_LD + a_r1] = rA1.y;
        As[buf][(a_c0 * 4 + 2) * AS_LD + a_r1] = rA1.z;
        As[buf][(a_c0 * 4 + 3) * AS_LD + a_r1] = rA1.w;
        *(float4*)&Bs[buf][b_r0][b_c4 * 4] = rB0;
        *(float4*)&Bs[buf][b_r1][b_c4 * 4] = rB1;
        *(float4*)&Bs[buf][b_r2][b_c4 * 4] = rB2;
        *(float4*)&Bs[buf][b_r3][b_c4 * 4] = rB3;
    };

    float acc[4][4];
    #pragma unroll
    for (int i = 0; i < 4; i++)
        #pragma unroll
        for (int j = 0; j < 4; j++) acc[i][j] = 0.0f;

    load_tiles(0);
    store_tiles(0);
    __syncthreads();

    const int NT = IN_DIM / GM_BK;
    for (int t = 0; t < NT; t++) {
        int buf = t & 1;
        if (t + 1 < NT) load_tiles((t + 1) * GM_BK);

        #pragma unroll
        for (int k = 0; k < GM_BK; k++) {
            float4 av = *(const float4*)&As[buf][k * AS_LD + trow * 4];
            float4 bv = *(const float4*)&Bs[buf][k][tcol * 4];
            float aa[4] = {av.x, av.y, av.z, av.w};
            float bb[4] = {bv.x, bv.y, bv.z, bv.w};
            #pragma unroll
            for (int i = 0; i < 4; i++)
                #pragma unroll
                for (int j = 0; j < 4; j++)
                    acc[i][j] = fmaf(aa[i], bb[j], acc[i][j]);
        }
        if (t + 1 < NT) store_tiles(buf ^ 1);
        __syncthreads();
    }

    #pragma unroll
    for (int i = 0; i < 4; i++) {
        int row = block_row + trow * 4 + i;
        float4 vv = make_float4(acc[i][0], acc[i][1], acc[i][2], acc[i][3]);
        *(float4*)(g_proj + (size_t)row * OUT_DIM + tcol * 4) = vv;

        float q0 = acc[i][0] * a_s[tcol * 4 + 0] + acc[i][1] * a_s[tcol * 4 + 1]
                 + acc[i][2] * a_s[tcol * 4 + 2] + acc[i][3] * a_s[tcol * 4 + 3];
        float q1 = acc[i][0] * a_s[64 + tcol * 4 + 0] + acc[i][1] * a_s[64 + tcol * 4 + 1]
                 + acc[i][2] * a_s[64 + tcol * 4 + 2] + acc[i][3] * a_s[64 + tcol * 4 + 3];
        #pragma unroll
        for (int o = 8; o > 0; o >>= 1) {
            q0 += __shfl_down_sync(0xffffffffu, q0, o, 16);
            q1 += __shfl_down_sync(0xffffffffu, q1, o, 16);
        }
        if (tcol == 0) { g_si[row] = q0; g_sj[row] = q1; }
    }
}

// ---------------------------------------------------------------------------
// Kernel 2: per-row sparse softmax-attention.
// NEW: the 32 KB adjacency row is fetched by ONE TMA bulk copy (UBLKCP) into
// smem — replaces 2048 per-thread LDG.128s (LSU-issue co-limiter identified
// in R9). Scan then runs from smem via conflict-free LDS.128; bitmask
// compaction / softmax / gather identical to R9 (proven, deterministic).
// ---------------------------------------------------------------------------
#define CAP 512   // mean deg 82, sd 9 -> 47 sigma headroom

__device__ __forceinline__ float leaky(float x) {
    return x > 0.0f ? x : SLOPE * x;
}

__device__ __forceinline__ float block_reduce(float v, float* s8, bool do_max)
{
    int lane = threadIdx.x & 31;
    int warp = threadIdx.x >> 5;
    #pragma unroll
    for (int o = 16; o > 0; o >>= 1) {
        float t = __shfl_xor_sync(0xffffffffu, v, o);
        v = do_max ? fmaxf(v, t) : (v + t);
    }
    __syncthreads();
    if (lane == 0) s8[warp] = v;
    __syncthreads();
    if (threadIdx.x == 0) {
        float r = s8[0];
        #pragma unroll
        for (int w = 1; w < 8; w++)
            r = do_max ? fmaxf(r, s8[w]) : (r + s8[w]);
        s8[0] = r;
    }
    __syncthreads();
    return s8[0];
}

__global__ __launch_bounds__(256) void attn_kernel(
    const unsigned* __restrict__ adj, float* __restrict__ out)
{
    __shared__ alignas(128) unsigned s_row[N_NODES];   // 32 KB row buffer
    __shared__ alignas(8)  unsigned long long s_mbar;  // mbarrier
    __shared__ int   s_idx[CAP];
    __shared__ float s_w[CAP];
    __shared__ float s_acc[4][OUT_DIM];
    __shared__ float s_red[8];
    __shared__ int   s_wsum[8];
    __shared__ int   s_woff[8];
    __shared__ int   s_cnt;

    const int row = blockIdx.x;
    const int tid = threadIdx.x;
    const int lane = tid & 31;
    const int warp = tid >> 5;

    // smem addresses for PTX
    unsigned mbar_addr, srow_addr;
    asm("{ .reg .u64 t; cvta.to.shared.u64 t, %1; cvt.u32.u64 %0, t; }"
        : "=r"(mbar_addr) : "l"(&s_mbar));
    asm("{ .reg .u64 t; cvta.to.shared.u64 t, %1; cvt.u32.u64 %0, t; }"
        : "=r"(srow_addr) : "l"(s_row));

    const unsigned* arow_g = adj + (size_t)row * N_NODES;   // 32768 B, 16B-aligned

    // ---- TMA bulk copy: one UBLKCP fetches the whole row into smem ----
    if (tid == 0) {
        asm volatile("mbarrier.init.shared.b64 [%0], 1;" :: "r"(mbar_addr) : "memory");
        asm volatile("fence.proxy.async.shared::cta;" ::: "memory");
        asm volatile("mbarrier.arrive.expect_tx.shared.b64 _, [%0], %1;"
                     :: "r"(mbar_addr), "r"(32768u) : "memory");
        asm volatile(
            "cp.async.bulk.shared::cta.global.mbarrier::complete_tx::bytes "
            "[%0], [%1], %2, [%3];"
            :: "r"(srow_addr), "l"(arow_g), "r"(32768u), "r"(mbar_addr)
            : "memory");
    }
    __syncthreads();   // mbarrier init visible to all before waiting
    {
        asm volatile(
            "{\n\t"
            ".reg .pred P;\n\t"
            "WAIT_%=:\n\t"
            "mbarrier.try_wait.parity.acquire.cta.shared::cta.b64 P, [%0], 0, 0x989680;\n\t"
            "@P bra.uni DONE_%=;\n\t"
            "bra.uni WAIT_%=;\n\t"
            "DONE_%=:\n\t"
            "}"
            :: "r"(mbar_addr) : "memory");
    }

    // ---- single pass over smem: pack nonzero flags into a register mask ----
    const uint4* srow4 = (const uint4*)s_row;
    unsigned mask = 0;
    #pragma unroll
    for (int it = 0; it < 8; it++) {
        uint4 v = srow4[tid + it * 256];
        unsigned b = (v.x != 0u ? 1u : 0u)
                   | (v.y != 0u ? 2u : 0u)
                   | (v.z != 0u ? 4u : 0u)
                   | (v.w != 0u ? 8u : 0u);
        mask |= b << (it * 4);
    }
    const int c = __popc(mask);

    // ---- block exclusive scan over per-thread counts ----
    int inc = c;
    #pragma unroll
    for (int o = 1; o < 32; o <<= 1) {
        int t = __shfl_up_sync(0xffffffffu, inc, o);
        if (lane >= o) inc += t;
    }
    if (lane == 31) s_wsum[warp] = inc;
    __syncthreads();
    if (tid == 0) {
        int s = 0;
        #pragma unroll
        for (int w = 0; w < 8; w++) { s_woff[w] = s; s += s_wsum[w]; }
        s_cnt = s;
    }
    __syncthreads();
    int off = s_woff[warp] + inc - c;
    const int cnt = s_cnt;

    // ---- compaction from the bitmask (ascending = deterministic order) ----
    if (cnt <= CAP) {
        unsigned m = mask;
        while (m) {
            int p = __ffs(m) - 1;
            m &= m - 1;
            s_idx[off++] = 4 * tid + (p >> 2) * 1024 + (p & 3);
        }
    }
    __syncthreads();

    const float si_r = g_si[row];
    const int   g    = tid >> 6;      // group 0..3
    const int   d    = tid & 63;      // output dim

    if (cnt == 0) {
        // softmax over all-NEG_BIG row is uniform: out = mean(proj)
        float acc = 0.0f;
        for (int j = g; j < N_NODES; j += 4)
            acc += g_proj[(size_t)j * OUT_DIM + d];
        s_acc[g][d] = acc;
        __syncthreads();
        if (g == 0) {
            float tot = s_acc[0][d] + s_acc[1][d] + s_acc[2][d] + s_acc[3][d];
            out[(size_t)row * OUT_DIM + d] = tot * (1.0f / (float)N_NODES);
        }
        return;
    }

    if (cnt <= CAP) {
        // ---- fast path: list-based softmax ----
        float lm = -INFINITY;
        for (int k = tid; k < cnt; k += 256) {
            float e = leaky(si_r + g_sj[s_idx[k]]);
            s_w[k] = e;
            lm = fmaxf(lm, e);
        }
        float m = block_reduce(lm, s_red, true);

        float ls = 0.0f;
        for (int k = tid; k < cnt; k += 256) {
            float w = __expf(s_w[k] - m);
            s_w[k] = w;
            ls += w;
        }
        float denom = block_reduce(ls, s_red, false);

        float acc = 0.0f;
        #pragma unroll 4
        for (int k = g; k < cnt; k += 4)
            acc += s_w[k] * g_proj[(size_t)s_idx[k] * OUT_DIM + d];
        s_acc[g][d] = acc;
        __syncthreads();
        if (g == 0) {
            float tot = s_acc[0][d] + s_acc[1][d] + s_acc[2][d] + s_acc[3][d];
            out[(size_t)row * OUT_DIM + d] = tot / denom;
        }
        return;
    }

    // ---- overflow fallback (cnt > CAP, ~never): rescan from smem ----
    float lm = -INFINITY;
    for (int j = tid; j < N_NODES; j += 256)
        if (s_row[j]) lm = fmaxf(lm, leaky(si_r + g_sj[j]));
    float m = block_reduce(lm, s_red, true);

    float ls = 0.0f;
    for (int j = tid; j < N_NODES; j += 256)
        if (s_row[j]) ls += __expf(leaky(si_r + g_sj[j]) - m);
    float denom = block_reduce(ls, s_red, false);

    float acc = 0.0f;
    for (int j = g; j < N_NODES; j += 4)
        if (s_row[j]) {
            float w = __expf(leaky(si_r + g_sj[j]) - m);
            acc += w * g_proj[(size_t)j * OUT_DIM + d];
        }
    s_acc[g][d] = acc;
    __syncthreads();
    if (g == 0) {
        float tot = s_acc[0][d] + s_acc[1][d] + s_acc[2][d] + s_acc[3][d];
        out[(size_t)row * OUT_DIM + d] = tot / denom;
    }
}

// ---------------------------------------------------------------------------
// Launch
// ---------------------------------------------------------------------------
extern "C" void kernel_launch(void* const* d_in, const int* in_sizes, int n_in,
                              void* d_out, int out_size)
{
    const float*    X   = (const float*)d_in[0];
    const unsigned* adj = (const unsigned*)d_in[1];   // bool widened to 32-bit
    const float*    W   = (const float*)d_in[2];
    const float*    a   = (const float*)d_in[3];
    float*          out = (float*)d_out;

    gemm_proj_kernel<<<N_NODES / GM_BM, 128>>>(X, W, a);
    attn_kernel<<<N_NODES, 256>>>(adj, out);
}

// round 11
// speedup vs baseline: 1.1620x; 1.1620x over previous
#include <cuda_runtime.h>
#include <cstdint>

// Problem constants (fixed by setup_inputs)
#define N_NODES 8192
#define IN_DIM  256
#define OUT_DIM 64
#define SLOPE   0.2f

// Scratch (allocation-free rule: __device__ globals)
__device__ float g_proj[N_NODES * OUT_DIM];   // 2 MB
__device__ float g_si[N_NODES];
__device__ float g_sj[N_NODES];

// ---------------------------------------------------------------------------
// Kernel 1: proj = X[8192,256] @ W[256,64] + fused s_i/s_j epilogue.
// (R8 version verbatim — measured ~10.4 us, frozen.)
// ---------------------------------------------------------------------------
#define GM_BM 32
#define GM_BK 32
#define AS_LD 36   // 32 + 4 pad

__global__ __launch_bounds__(128) void gemm_proj_kernel(
    const float* __restrict__ X, const float* __restrict__ W,
    const float* __restrict__ a)
{
    __shared__ float As[2][GM_BK * AS_LD];   // [k][m], padded
    __shared__ float Bs[2][GM_BK][OUT_DIM];  // [k][n]
    __shared__ float a_s[2 * OUT_DIM];

    const int tid = threadIdx.x;
    const int block_row = blockIdx.x * GM_BM;
    const int trow = tid >> 4;   // 0..7
    const int tcol = tid & 15;   // 0..15

    a_s[tid] = a[tid];

    const int a_r0 = tid >> 3;
    const int a_c0 = tid & 7;
    const int a_r1 = (tid + 128) >> 3;
    const int b_c4 = tid & 15;
    const int b_r0 = tid >> 4;
    const int b_r1 = (tid + 128) >> 4;
    const int b_r2 = (tid + 256) >> 4;
    const int b_r3 = (tid + 384) >> 4;

    float4 rA0, rA1, rB0, rB1, rB2, rB3;

    auto load_tiles = [&](int k0) {
        rA0 = *(const float4*)(X + (size_t)(block_row + a_r0) * IN_DIM + k0 + a_c0 * 4);
        rA1 = *(const float4*)(X + (size_t)(block_row + a_r1) * IN_DIM + k0 + a_c0 * 4);
        rB0 = *(const float4*)(W + (size_t)(k0 + b_r0) * OUT_DIM + b_c4 * 4);
        rB1 = *(const float4*)(W + (size_t)(k0 + b_r1) * OUT_DIM + b_c4 * 4);
        rB2 = *(const float4*)(W + (size_t)(k0 + b_r2) * OUT_DIM + b_c4 * 4);
        rB3 = *(const float4*)(W + (size_t)(k0 + b_r3) * OUT_DIM + b_c4 * 4);
    };
    auto store_tiles = [&](int buf) {
        As[buf][(a_c0 * 4 + 0) * AS_LD + a_r0] = rA0.x;
        As[buf][(a_c0 * 4 + 1) * AS_LD + a_r0] = rA0.y;
        As[buf][(a_c0 * 4 + 2) * AS_LD + a_r0] = rA0.z;
        As[buf][(a_c0 * 4 + 3) * AS_LD + a_r0] = rA0.w;
        As[buf][(a_c0 * 4 + 0) * AS_LD + a_r1] = rA1.x;
        As[buf][(a_c0 * 4 + 1) * AS_LD + a_r1] = rA1.y;
        As[buf][(a_c0 * 4 + 2) * AS_LD + a_r1] = rA1.z;
        As[buf][(a_c0 * 4 + 3) * AS_LD + a_r1] = rA1.w;
        *(float4*)&Bs[buf][b_r0][b_c4 * 4] = rB0;
        *(float4*)&Bs[buf][b_r1][b_c4 * 4] = rB1;
        *(float4*)&Bs[buf][b_r2][b_c4 * 4] = rB2;
        *(float4*)&Bs[buf][b_r3][b_c4 * 4] = rB3;
    };

    float acc[4][4];
    #pragma unroll
    for (int i = 0; i < 4; i++)
        #pragma unroll
        for (int j = 0; j < 4; j++) acc[i][j] = 0.0f;

    load_tiles(0);
    store_tiles(0);
    __syncthreads();

    const int NT = IN_DIM / GM_BK;
    for (int t = 0; t < NT; t++) {
        int buf = t & 1;
        if (t + 1 < NT) load_tiles((t + 1) * GM_BK);

        #pragma unroll
        for (int k = 0; k < GM_BK; k++) {
            float4 av = *(const float4*)&As[buf][k * AS_LD + trow * 4];
            float4 bv = *(const float4*)&Bs[buf][k][tcol * 4];
            float aa[4] = {av.x, av.y, av.z, av.w};
            float bb[4] = {bv.x, bv.y, bv.z, bv.w};
            #pragma unroll
            for (int i = 0; i < 4; i++)
                #pragma unroll
                for (int j = 0; j < 4; j++)
                    acc[i][j] = fmaf(aa[i], bb[j], acc[i][j]);
        }
        if (t + 1 < NT) store_tiles(buf ^ 1);
        __syncthreads();
    }

    #pragma unroll
    for (int i = 0; i < 4; i++) {
        int row = block_row + trow * 4 + i;
        float4 vv = make_float4(acc[i][0], acc[i][1], acc[i][2], acc[i][3]);
        *(float4*)(g_proj + (size_t)row * OUT_DIM + tcol * 4) = vv;

        float q0 = acc[i][0] * a_s[tcol * 4 + 0] + acc[i][1] * a_s[tcol * 4 + 1]
                 + acc[i][2] * a_s[tcol * 4 + 2] + acc[i][3] * a_s[tcol * 4 + 3];
        float q1 = acc[i][0] * a_s[64 + tcol * 4 + 0] + acc[i][1] * a_s[64 + tcol * 4 + 1]
                 + acc[i][2] * a_s[64 + tcol * 4 + 2] + acc[i][3] * a_s[64 + tcol * 4 + 3];
        #pragma unroll
        for (int o = 8; o > 0; o >>= 1) {
            q0 += __shfl_down_sync(0xffffffffu, q0, o, 16);
            q1 += __shfl_down_sync(0xffffffffu, q1, o, 16);
        }
        if (tcol == 0) { g_si[row] = q0; g_sj[row] = q1; }
    }
}

// ---------------------------------------------------------------------------
// Kernel 2: per-row sparse softmax-attention.
// R9 logic, reshaped to 128-thread blocks @ 12 blocks/SM: doubles the number
// of concurrently-scanning rows per SM (the quantity that sets DRAM%).
// Scan: 16 uint4/thread in two batches of 8 -> 64-bit flag mask.
// Gather: float2 loads, 4 k-groups (k%4) x 32 dim-pairs -> identical per-dim
// summation order to R9 (bit-identical output), half the load instructions.
// ---------------------------------------------------------------------------
#define CAP 512   // mean deg 82, sd 9

__device__ __forceinline__ float leaky(float x) {
    return x > 0.0f ? x : SLOPE * x;
}

// 4-warp block reduce
__device__ __forceinline__ float block_reduce4(float v, float* s4, bool do_max)
{
    int lane = threadIdx.x & 31;
    int warp = threadIdx.x >> 5;
    #pragma unroll
    for (int o = 16; o > 0; o >>= 1) {
        float t = __shfl_xor_sync(0xffffffffu, v, o);
        v = do_max ? fmaxf(v, t) : (v + t);
    }
    __syncthreads();
    if (lane == 0) s4[warp] = v;
    __syncthreads();
    float r = do_max ? fmaxf(fmaxf(s4[0], s4[1]), fmaxf(s4[2], s4[3]))
                     : (s4[0] + s4[1]) + (s4[2] + s4[3]);
    return r;
}

__global__ __launch_bounds__(128, 12) void attn_kernel(
    const unsigned* __restrict__ adj, float* __restrict__ out)
{
    __shared__ int   s_idx[CAP];
    __shared__ float s_w[CAP];
    __shared__ float2 s_acc[4][32];     // [k-group][dim pair]
    __shared__ float s_red[4];
    __shared__ int   s_wsum[4];
    __shared__ int   s_woff[4];
    __shared__ int   s_cnt;

    const int row = blockIdx.x;
    const int tid = threadIdx.x;
    const int lane = tid & 31;
    const int warp = tid >> 5;

    const unsigned* arow = adj + (size_t)row * N_NODES;   // 8192 words = 32 KB
    const uint4* arow4 = (const uint4*)arow;              // 2048 uint4

    // ---- single pass: 16 uint4/thread (2 batches of 8) -> 64-bit mask ----
    unsigned long long mask = 0ull;
    #pragma unroll
    for (int b = 0; b < 2; b++) {
        uint4 v[8];
        #pragma unroll
        for (int it = 0; it < 8; it++)
            v[it] = arow4[tid + (b * 8 + it) * 128];
        #pragma unroll
        for (int it = 0; it < 8; it++) {
            unsigned bits = (v[it].x != 0u ? 1u : 0u)
                          | (v[it].y != 0u ? 2u : 0u)
                          | (v[it].z != 0u ? 4u : 0u)
                          | (v[it].w != 0u ? 8u : 0u);
            mask |= (unsigned long long)bits << ((b * 8 + it) * 4);
        }
    }
    const int c = __popcll(mask);

    // ---- block exclusive scan over per-thread counts (4 warps) ----
    int inc = c;
    #pragma unroll
    for (int o = 1; o < 32; o <<= 1) {
        int t = __shfl_up_sync(0xffffffffu, inc, o);
        if (lane >= o) inc += t;
    }
    if (lane == 31) s_wsum[warp] = inc;
    __syncthreads();
    if (tid == 0) {
        int s = 0;
        #pragma unroll
        for (int w = 0; w < 4; w++) { s_woff[w] = s; s += s_wsum[w]; }
        s_cnt = s;
    }
    __syncthreads();
    int off = s_woff[warp] + inc - c;
    const int cnt = s_cnt;

    // ---- compaction from bitmask (ascending -> deterministic) ----
    if (cnt <= CAP) {
        unsigned long long m = mask;
        while (m) {
            int p = __ffsll(m) - 1;
            m &= m - 1;
            // uint4 index = tid + (p>>2)*128 ; word = 4*that + (p&3)
            s_idx[off++] = 4 * tid + (p >> 2) * 512 + (p & 3);
        }
    }
    __syncthreads();

    const float si_r = g_si[row];
    const int   gg   = tid >> 5;       // k-group 0..3
    const int   pr   = tid & 31;       // dim pair 0..31 (dims 2*pr, 2*pr+1)
    const float2* proj2 = (const float2*)g_proj;

    if (cnt == 0) {
        // softmax over all-NEG_BIG row is uniform: out = mean(proj)
        float2 acc = make_float2(0.0f, 0.0f);
        for (int j = gg; j < N_NODES; j += 4) {
            float2 p = proj2[(size_t)j * 32 + pr];
            acc.x += p.x; acc.y += p.y;
        }
        s_acc[gg][pr] = acc;
        __syncthreads();
        if (tid < 64) {
            int pp = tid >> 1, comp = tid & 1;
            float tot = comp == 0
                ? (s_acc[0][pp].x + s_acc[1][pp].x + s_acc[2][pp].x + s_acc[3][pp].x)
                : (s_acc[0][pp].y + s_acc[1][pp].y + s_acc[2][pp].y + s_acc[3][pp].y);
            out[(size_t)row * OUT_DIM + tid] = tot * (1.0f / (float)N_NODES);
        }
        return;
    }

    if (cnt <= CAP) {
        // ---- fast path: list-based softmax ----
        float lm = -INFINITY;
        for (int k = tid; k < cnt; k += 128) {
            float e = leaky(si_r + g_sj[s_idx[k]]);
            s_w[k] = e;
            lm = fmaxf(lm, e);
        }
        float m = block_reduce4(lm, s_red, true);

        float ls = 0.0f;
        for (int k = tid; k < cnt; k += 128) {
            float w = __expf(s_w[k] - m);
            s_w[k] = w;
            ls += w;
        }
        float denom = block_reduce4(ls, s_red, false);

        float2 acc = make_float2(0.0f, 0.0f);
        #pragma unroll 4
        for (int k = gg; k < cnt; k += 4) {
            float wv = s_w[k];
            float2 p = proj2[(size_t)s_idx[k] * 32 + pr];
            acc.x = fmaf(wv, p.x, acc.x);
            acc.y = fmaf(wv, p.y, acc.y);
        }
        s_acc[gg][pr] = acc;
        __syncthreads();
        if (tid < 64) {
            int pp = tid >> 1, comp = tid & 1;
            float tot = comp == 0
                ? (s_acc[0][pp].x + s_acc[1][pp].x + s_acc[2][pp].x + s_acc[3][pp].x)
                : (s_acc[0][pp].y + s_acc[1][pp].y + s_acc[2][pp].y + s_acc[3][pp].y);
            out[(size_t)row * OUT_DIM + tid] = tot / denom;
        }
        return;
    }

    // ---- overflow fallback (cnt > CAP, ~never): direct rescan ----
    float lm = -INFINITY;
    for (int j = tid; j < N_NODES; j += 128)
        if (arow[j]) lm = fmaxf(lm, leaky(si_r + g_sj[j]));
    float m = block_reduce4(lm, s_red, true);

    float ls = 0.0f;
    for (int j = tid; j < N_NODES; j += 128)
        if (arow[j]) ls += __expf(leaky(si_r + g_sj[j]) - m);
    float denom = block_reduce4(ls, s_red, false);

    float2 acc = make_float2(0.0f, 0.0f);
    for (int j = gg; j < N_NODES; j += 4)
        if (arow[j]) {
            float w = __expf(leaky(si_r + g_sj[j]) - m);
            float2 p = proj2[(size_t)j * 32 + pr];
            acc.x = fmaf(w, p.x, acc.x);
            acc.y = fmaf(w, p.y, acc.y);
        }
    s_acc[gg][pr] = acc;
    __syncthreads();
    if (tid < 64) {
        int pp = tid >> 1, comp = tid & 1;
        float tot = comp == 0
            ? (s_acc[0][pp].x + s_acc[1][pp].x + s_acc[2][pp].x + s_acc[3][pp].x)
            : (s_acc[0][pp].y + s_acc[1][pp].y + s_acc[2][pp].y + s_acc[3][pp].y);
        out[(size_t)row * OUT_DIM + tid] = tot / denom;
    }
}

// ---------------------------------------------------------------------------
// Launch
// ---------------------------------------------------------------------------
extern "C" void kernel_launch(void* const* d_in, const int* in_sizes, int n_in,
                              void* d_out, int out_size)
{
    const float*    X   = (const float*)d_in[0];
    const unsigned* adj = (const unsigned*)d_in[1];   // bool widened to 32-bit
    const float*    W   = (const float*)d_in[2];
    const float*    a   = (const float*)d_in[3];
    float*          out = (float*)d_out;

    gemm_proj_kernel<<<N_NODES / GM_BM, 128>>>(X, W, a);
    attn_kernel<<<N_NODES, 128>>>(adj, out);
}